// round 1
// baseline (speedup 1.0000x reference)
#include <cuda_runtime.h>

// DigitCapsules dynamic routing, GB300 sm_103a
// B=256 batch, C=10 classes, I=1152 input caps, DI=8, DO=16, 3 routing iters.
//
// Key identity: blog_t[b,c,i] = <u_hat[b,c,i,:], (v_0+...+v_{t-1})[b,c,:]>
// so routing state is just vacc[b,c,:] = sum of v's (40960 floats), and with
// vacc=0 the first call reproduces iteration 0 (softmax(0) = 1/10) exactly.
// => one iteration kernel, launched 3 times.

#define BSZ  256
#define CCL  10
#define ICAP 1152
#define DOV  16
#define DIV  8

// Scratch (static device allocations; no runtime alloc).
__device__ __align__(256) float g_uhat[(size_t)BSZ * CCL * ICAP * DOV]; // ~189 MB
__device__ __align__(256) float g_vacc[BSZ * CCL * DOV];                // 160 KB

// ---------------------------------------------------------------------------
// Zero the routing state each launch (graph is replayed; no static guards).
// ---------------------------------------------------------------------------
__global__ void zero_vacc_kernel() {
    int t = blockIdx.x * blockDim.x + threadIdx.x;
    if (t < BSZ * CCL * DOV) g_vacc[t] = 0.0f;
}

// ---------------------------------------------------------------------------
// K_uhat: u_hat[b,c,i,do] = sum_k W[c,i,0,do,k] * x[b,i,k]
// grid = I (one block per input capsule), 160 threads = (c,do).
// x[:, i, :] staged in smem (broadcast reads); W row held in registers.
// ---------------------------------------------------------------------------
__global__ __launch_bounds__(160) void uhat_kernel(
    const float* __restrict__ x, const float* __restrict__ W)
{
    const int i = blockIdx.x;
    const int t = threadIdx.x;       // 0..159
    const int c = t >> 4;            // 0..9
    const int d = t & 15;            // 0..15

    __shared__ float4 xs[BSZ * 2];   // x[b][k] as 2 float4 per b

    // Cooperative load of x[:, i, :]  (256 b * 8 floats = 8 KB)
    for (int e = t; e < BSZ * 2; e += 160) {
        int b = e >> 1, half = e & 1;
        xs[e] = *reinterpret_cast<const float4*>(
            x + (size_t)b * (ICAP * DIV) + (size_t)i * DIV + half * 4);
    }

    // This thread's W row: W[c, i, 0, d, 0..7]
    const float* wp = W + ((((size_t)c * ICAP + i) * DOV) + d) * DIV;
    const float4 w0 = *reinterpret_cast<const float4*>(wp);
    const float4 w1 = *reinterpret_cast<const float4*>(wp + 4);

    __syncthreads();

    const size_t base    = ((size_t)c * ICAP + i) * DOV + d; // [b][c][i][do]
    const size_t bstride = (size_t)CCL * ICAP * DOV;

    #pragma unroll 4
    for (int b = 0; b < BSZ; b++) {
        float4 x0 = xs[b * 2];
        float4 x1 = xs[b * 2 + 1];
        float v = w0.x * x0.x;
        v = fmaf(w0.y, x0.y, v);
        v = fmaf(w0.z, x0.z, v);
        v = fmaf(w0.w, x0.w, v);
        v = fmaf(w1.x, x1.x, v);
        v = fmaf(w1.y, x1.y, v);
        v = fmaf(w1.z, x1.z, v);
        v = fmaf(w1.w, x1.w, v);
        g_uhat[base + (size_t)b * bstride] = v;
    }
}

// ---------------------------------------------------------------------------
// K_iter: one routing iteration.
//   a[c,i]   = <u_hat[b,c,i,:], vacc[b,c,:]>
//   w[c,i]   = softmax_c(a)
//   s[c,:]   = sum_i w[c,i] * u_hat[b,c,i,:]
//   v        = squash(s);  d_out <- v;  vacc <- vacc + v
// grid = B (one block per batch), 320 threads: warp = class, lane = i slot.
// 36 tiles of 32 i's, software-pipelined float4 loads.
// ---------------------------------------------------------------------------
__global__ __launch_bounds__(320, 2) void iter_kernel(float* __restrict__ vout)
{
    const int b  = blockIdx.x;
    const int c  = threadIdx.x >> 5;   // warp id = class
    const int ii = threadIdx.x & 31;   // lane = i within tile

    __shared__ float a_s[CCL][33];
    __shared__ float e_s[CCL][33];

    // vacc[b,c,:] in registers (identical across lanes of the warp)
    float vr[DOV];
    {
        const float* vp = g_vacc + ((size_t)b * CCL + c) * DOV;
        #pragma unroll
        for (int j = 0; j < DOV; j++) vr[j] = vp[j];
    }

    float sac[DOV];
    #pragma unroll
    for (int j = 0; j < DOV; j++) sac[j] = 0.0f;

    const float* ub = g_uhat + ((size_t)b * CCL + c) * (size_t)ICAP * DOV;

    const int NT = ICAP / 32;  // 36 tiles
    float4 u0, u1, u2, u3;
    {
        const float4* p = reinterpret_cast<const float4*>(ub + (size_t)ii * DOV);
        u0 = p[0]; u1 = p[1]; u2 = p[2]; u3 = p[3];
    }

    for (int ti = 0; ti < NT; ti++) {
        // Prefetch next tile (clamped; redundant load on last tile is harmless)
        const int tn = (ti + 1 < NT) ? (ti + 1) : (NT - 1);
        const float4* pn = reinterpret_cast<const float4*>(
            ub + (size_t)(tn * 32 + ii) * DOV);
        float4 n0 = pn[0], n1 = pn[1], n2 = pn[2], n3 = pn[3];

        // agreement a = <u, vacc>
        float a = u0.x * vr[0];
        a = fmaf(u0.y, vr[1], a);  a = fmaf(u0.z, vr[2], a);  a = fmaf(u0.w, vr[3], a);
        a = fmaf(u1.x, vr[4], a);  a = fmaf(u1.y, vr[5], a);  a = fmaf(u1.z, vr[6], a);
        a = fmaf(u1.w, vr[7], a);  a = fmaf(u2.x, vr[8], a);  a = fmaf(u2.y, vr[9], a);
        a = fmaf(u2.z, vr[10], a); a = fmaf(u2.w, vr[11], a); a = fmaf(u3.x, vr[12], a);
        a = fmaf(u3.y, vr[13], a); a = fmaf(u3.z, vr[14], a); a = fmaf(u3.w, vr[15], a);

        a_s[c][ii] = a;
        __syncthreads();

        // softmax over classes for this i (max redundantly; 1 exp per thread)
        float m = a_s[0][ii];
        #pragma unroll
        for (int cc = 1; cc < CCL; cc++) m = fmaxf(m, a_s[cc][ii]);
        float e = __expf(a - m);
        e_s[c][ii] = e;
        __syncthreads();

        float Z = 0.0f;
        #pragma unroll
        for (int cc = 0; cc < CCL; cc++) Z += e_s[cc][ii];
        float w = __fdividef(e, Z);

        // s accumulation
        sac[0]  = fmaf(w, u0.x, sac[0]);  sac[1]  = fmaf(w, u0.y, sac[1]);
        sac[2]  = fmaf(w, u0.z, sac[2]);  sac[3]  = fmaf(w, u0.w, sac[3]);
        sac[4]  = fmaf(w, u1.x, sac[4]);  sac[5]  = fmaf(w, u1.y, sac[5]);
        sac[6]  = fmaf(w, u1.z, sac[6]);  sac[7]  = fmaf(w, u1.w, sac[7]);
        sac[8]  = fmaf(w, u2.x, sac[8]);  sac[9]  = fmaf(w, u2.y, sac[9]);
        sac[10] = fmaf(w, u2.z, sac[10]); sac[11] = fmaf(w, u2.w, sac[11]);
        sac[12] = fmaf(w, u3.x, sac[12]); sac[13] = fmaf(w, u3.y, sac[13]);
        sac[14] = fmaf(w, u3.z, sac[14]); sac[15] = fmaf(w, u3.w, sac[15]);

        u0 = n0; u1 = n1; u2 = n2; u3 = n3;
    }

    // warp butterfly reduce over the 32 i-slots (all lanes end with full sum)
    #pragma unroll
    for (int off = 16; off > 0; off >>= 1) {
        #pragma unroll
        for (int j = 0; j < DOV; j++)
            sac[j] += __shfl_xor_sync(0xffffffffu, sac[j], off);
    }

    // squash: v = s * sqrt(|s|^2) / (1 + |s|^2)
    float sq = 0.0f;
    #pragma unroll
    for (int j = 0; j < DOV; j++) sq = fmaf(sac[j], sac[j], sq);
    float scale = __fdividef(sqrtf(sq), 1.0f + sq);

    if (ii == 0) {
        float* vo = vout   + ((size_t)b * CCL + c) * DOV;
        float* va = g_vacc + ((size_t)b * CCL + c) * DOV;
        #pragma unroll
        for (int j = 0; j < DOV; j++) {
            float vj = sac[j] * scale;
            vo[j] = vj;            // v of this iteration (final call = answer)
            va[j] = vr[j] + vj;    // running sum for next iteration's logits
        }
    }
}

// ---------------------------------------------------------------------------
extern "C" void kernel_launch(void* const* d_in, const int* in_sizes, int n_in,
                              void* d_out, int out_size)
{
    const float* x = (const float*)d_in[0];
    const float* W = (const float*)d_in[1];
    // Defensive: identify by element counts (x: 2359296, W: 1474560)
    if (in_sizes[0] == CCL * ICAP * DOV * DIV) {
        const float* t = x; x = W; W = t;
    }
    float* out = (float*)d_out;

    zero_vacc_kernel<<<(BSZ * CCL * DOV + 255) / 256, 256>>>();
    uhat_kernel<<<ICAP, 160>>>(x, W);
    iter_kernel<<<BSZ, 320>>>(out);   // iter 0 (vacc=0 -> uniform softmax)
    iter_kernel<<<BSZ, 320>>>(out);   // iter 1
    iter_kernel<<<BSZ, 320>>>(out);   // iter 2 -> final v in d_out
}

// round 3
// speedup vs baseline: 1.4333x; 1.4333x over previous
#include <cuda_runtime.h>
#include <cuda_fp16.h>
#include <cstdint>

// DigitCapsules dynamic routing, GB300 sm_103a
// B=256, C=10, I=1152, DI=8, DO=16, 3 routing iterations.
//
// Identity: blog_t[b,c,i] = <u_hat[b,c,i,:], sum_{tau<t} v_tau[b,c,:]>.
// Per-iteration state is s_t[b,c,:] (pre-squash sums). Iteration t recomputes
// vacc = sum_{tau<t} squash(s_tau) in its prologue from L2-resident g_s.
// Iteration 0 has uniform weights (0.1) -> pure streaming sum, no softmax.
//
// u_hat stored fp16 (fp32 compute, single rounding): 94.5 MB, fits in L2, so
// iter passes read at LTS bandwidth instead of HBM.

#define BSZ  256
#define CCL  10
#define ICAP 1152
#define DOV  16
#define DIV  8
#define NSPLIT 4                      // i-slices per batch in iter kernels
#define ISL  (ICAP / NSPLIT)          // 288
#define NT   (ISL / 32)               // 9 tiles of 32 i's

__device__ __align__(256) __half g_uhat[(size_t)BSZ * CCL * ICAP * DOV]; // 94.4 MB
__device__ __align__(256) float g_s[3 * BSZ * CCL * DOV];                // 480 KB

static __device__ __forceinline__ unsigned int pack_h2(float a, float b) {
    __half2 h = __floats2half2_rn(a, b);
    return *reinterpret_cast<unsigned int*>(&h);
}

// ---------------------------------------------------------------------------
// Zero the three s-slots each replay.
// ---------------------------------------------------------------------------
__global__ void zero_s_kernel() {
    int t = blockIdx.x * blockDim.x + threadIdx.x;
    if (t < 3 * BSZ * CCL * DOV) g_s[t] = 0.0f;
}

// ---------------------------------------------------------------------------
// K_uhat: u_hat[b,c,i,do] = sum_k W[c,i,0,do,k] * x[b,i,k]   (fp32 -> fp16)
// grid = I (block per input capsule), 256 threads = b.
// W rows for this i staged in smem (broadcast LDS.128); x row in registers.
// Stores: 2x STG.128 per (b,c) -- fully vectorized.
// ---------------------------------------------------------------------------
__global__ __launch_bounds__(256) void uhat_kernel(
    const float* __restrict__ x, const float* __restrict__ W)
{
    const int i = blockIdx.x;
    const int b = threadIdx.x;

    __shared__ float4 Ws[CCL * DOV * 2];   // [c][d][half4] : 5120 B

    for (int f = threadIdx.x; f < CCL * DOV * 2; f += 256) {
        int c = f >> 5, rem = f & 31, d = rem >> 1, h = rem & 1;
        Ws[f] = *reinterpret_cast<const float4*>(
            W + ((((size_t)c * ICAP + i) * DOV) + d) * DIV + h * 4);
    }

    const float* xp = x + (size_t)b * (ICAP * DIV) + (size_t)i * DIV;
    const float4 x0 = *reinterpret_cast<const float4*>(xp);
    const float4 x1 = *reinterpret_cast<const float4*>(xp + 4);

    __syncthreads();

    __half* up = g_uhat + (size_t)b * (CCL * ICAP * DOV) + (size_t)i * DOV;

    #pragma unroll
    for (int c = 0; c < CCL; c++) {
        float r[DOV];
        #pragma unroll
        for (int d = 0; d < DOV; d++) {
            float4 w0 = Ws[c * 32 + d * 2];
            float4 w1 = Ws[c * 32 + d * 2 + 1];
            float v = w0.x * x0.x;
            v = fmaf(w0.y, x0.y, v); v = fmaf(w0.z, x0.z, v); v = fmaf(w0.w, x0.w, v);
            v = fmaf(w1.x, x1.x, v); v = fmaf(w1.y, x1.y, v);
            v = fmaf(w1.z, x1.z, v); v = fmaf(w1.w, x1.w, v);
            r[d] = v;
        }
        uint4 q0, q1;
        q0.x = pack_h2(r[0],  r[1]);  q0.y = pack_h2(r[2],  r[3]);
        q0.z = pack_h2(r[4],  r[5]);  q0.w = pack_h2(r[6],  r[7]);
        q1.x = pack_h2(r[8],  r[9]);  q1.y = pack_h2(r[10], r[11]);
        q1.z = pack_h2(r[12], r[13]); q1.w = pack_h2(r[14], r[15]);
        __half* o = up + (size_t)c * (ICAP * DOV);
        *reinterpret_cast<uint4*>(o)     = q0;
        *reinterpret_cast<uint4*>(o + 8) = q1;
    }
}

// ---------------------------------------------------------------------------
// squash helper: v = s * sqrt(|s|^2) / (1 + |s|^2)
// ---------------------------------------------------------------------------
static __device__ __forceinline__ void squash16(const float* __restrict__ s,
                                                float* __restrict__ v) {
    float sq = 0.0f;
    #pragma unroll
    for (int j = 0; j < DOV; j++) sq = fmaf(s[j], s[j], sq);
    float scale = __fdividef(sqrtf(sq), 1.0f + sq);
    #pragma unroll
    for (int j = 0; j < DOV; j++) v[j] = s[j] * scale;
}

// ---------------------------------------------------------------------------
// K_iter<NPREV>: one routing iteration (iteration index = NPREV).
//   vacc = sum_{t<NPREV} squash(g_s[t][b,c,:])   (prologue, L2 reads)
//   a    = <u_hat, vacc>; w = softmax_c(a)       (NPREV=0: w = 0.1 exactly)
//   g_s[NPREV][b,c,:] += sum_i w * u_hat          (atomic partials)
// grid = B*NSPLIT, 320 threads: warp = class, lane = i slot, 9 tiles.
// Software-pipelined fp16 tile loads; double-buffered e_s -> 1 bar/tile.
// ---------------------------------------------------------------------------
template <int NPREV>
__global__ __launch_bounds__(320, 2) void iter_kernel()
{
    const int blk = blockIdx.x;
    const int b   = blk >> 2;
    const int sl  = blk & (NSPLIT - 1);
    const int c   = threadIdx.x >> 5;
    const int ii  = threadIdx.x & 31;

    __shared__ float e_s[2][CCL][33];

    // vacc from prior iterations' s-slots (broadcast loads)
    float vr[DOV];
    #pragma unroll
    for (int j = 0; j < DOV; j++) vr[j] = 0.0f;
    #pragma unroll
    for (int t = 0; t < NPREV; t++) {
        const float* sp = g_s + ((size_t)t * BSZ * CCL + (size_t)b * CCL + c) * DOV;
        float s[DOV], v[DOV];
        #pragma unroll
        for (int j = 0; j < DOV; j++) s[j] = sp[j];
        squash16(s, v);
        #pragma unroll
        for (int j = 0; j < DOV; j++) vr[j] += v[j];
    }

    float sac[DOV];
    #pragma unroll
    for (int j = 0; j < DOV; j++) sac[j] = 0.0f;

    const __half* ub = g_uhat + ((size_t)b * CCL + c) * (size_t)ICAP * DOV
                              + (size_t)sl * ISL * DOV;

    const uint4* p0 = reinterpret_cast<const uint4*>(ub + (size_t)ii * DOV);
    uint4 ua = p0[0], ubx = p0[1];

    for (int ti = 0; ti < NT; ti++) {
        // prefetch next tile (clamped duplicate on last tile)
        const int tn = (ti + 1 < NT) ? (ti + 1) : (NT - 1);
        const uint4* pn = reinterpret_cast<const uint4*>(
            ub + (size_t)(tn * 32 + ii) * DOV);
        uint4 na = pn[0], nb = pn[1];

        // unpack fp16 -> fp32
        float u[DOV];
        {
            const __half2* ha = reinterpret_cast<const __half2*>(&ua);
            const __half2* hb = reinterpret_cast<const __half2*>(&ubx);
            #pragma unroll
            for (int q = 0; q < 4; q++) {
                float2 f = __half22float2(ha[q]);
                u[q * 2] = f.x; u[q * 2 + 1] = f.y;
            }
            #pragma unroll
            for (int q = 0; q < 4; q++) {
                float2 f = __half22float2(hb[q]);
                u[8 + q * 2] = f.x; u[8 + q * 2 + 1] = f.y;
            }
        }

        float w;
        if (NPREV == 0) {
            w = 0.1f;   // softmax of all-zero logits over 10 classes
        } else {
            float a = u[0] * vr[0];
            #pragma unroll
            for (int j = 1; j < DOV; j++) a = fmaf(u[j], vr[j], a);
            // |a| <= |u||vacc| ~ 35 -> exp safe in fp32 without max-subtract
            float e = __expf(a);
            const int p = ti & 1;
            e_s[p][c][ii] = e;
            __syncthreads();
            float Z = e_s[p][0][ii];
            #pragma unroll
            for (int cc = 1; cc < CCL; cc++) Z += e_s[p][cc][ii];
            w = __fdividef(e, Z);
        }

        #pragma unroll
        for (int j = 0; j < DOV; j++) sac[j] = fmaf(w, u[j], sac[j]);

        ua = na; ubx = nb;
    }

    // butterfly reduce over 32 i-lanes
    #pragma unroll
    for (int off = 16; off > 0; off >>= 1) {
        #pragma unroll
        for (int j = 0; j < DOV; j++)
            sac[j] += __shfl_xor_sync(0xffffffffu, sac[j], off);
    }

    if (ii == 0) {
        float* sp = g_s + ((size_t)NPREV * BSZ * CCL + (size_t)b * CCL + c) * DOV;
        #pragma unroll
        for (int j = 0; j < DOV; j++) atomicAdd(sp + j, sac[j]);
    }
}

// ---------------------------------------------------------------------------
// Final squash: d_out = squash(g_s[2])   [B, C, 1, DO]
// ---------------------------------------------------------------------------
__global__ __launch_bounds__(256) void squash_out_kernel(float* __restrict__ out)
{
    int t = blockIdx.x * blockDim.x + threadIdx.x;   // (b,c) pair, 2560 total
    if (t >= BSZ * CCL) return;
    const float* sp = g_s + ((size_t)2 * BSZ * CCL + t) * DOV;
    float s[DOV], v[DOV];
    #pragma unroll
    for (int j = 0; j < DOV; j++) s[j] = sp[j];
    squash16(s, v);
    float* op = out + (size_t)t * DOV;
    #pragma unroll
    for (int j = 0; j < DOV; j++) op[j] = v[j];
}

// ---------------------------------------------------------------------------
extern "C" void kernel_launch(void* const* d_in, const int* in_sizes, int n_in,
                              void* d_out, int out_size)
{
    const float* x = (const float*)d_in[0];
    const float* W = (const float*)d_in[1];
    if (in_sizes[0] == CCL * ICAP * DOV * DIV) {  // defensively identify by size
        const float* t = x; x = W; W = t;
    }
    float* out = (float*)d_out;

    zero_s_kernel<<<(3 * BSZ * CCL * DOV + 1023) / 1024, 1024>>>();
    uhat_kernel<<<ICAP, 256>>>(x, W);
    iter_kernel<0><<<BSZ * NSPLIT, 320>>>();
    iter_kernel<1><<<BSZ * NSPLIT, 320>>>();
    iter_kernel<2><<<BSZ * NSPLIT, 320>>>();
    squash_out_kernel<<<(BSZ * CCL + 255) / 256, 256>>>(out);
}

// round 4
// speedup vs baseline: 1.8089x; 1.2621x over previous
#include <cuda_runtime.h>
#include <cuda_fp16.h>
#include <cstdint>

// DigitCapsules dynamic routing, GB300 sm_103a
// B=256, C=10, I=1152, DI=8, DO=16, 3 routing iterations.
//
// u_hat = W@x materialized once in fp16 (fp32 compute, one rounding): 94.4 MB.
// Routing is independent per batch element -> ONE persistent kernel, one block
// per b, all 3 iterations fused. vacc state lives in warp registers (warp =
// class). u_hat[b] (368 KB) is read 3x with short reuse distance -> L2-resident
// for iterations 1-2 instead of HBM re-streaming.

#define BSZ  256
#define CCL  10
#define ICAP 1152
#define DOV  16
#define DIV  8
#define NT   (ICAP / 32)   // 36 tiles of 32 input capsules

__device__ __align__(256) __half g_uhat[(size_t)BSZ * CCL * ICAP * DOV]; // 94.4 MB

static __device__ __forceinline__ unsigned int pack_h2(float a, float b) {
    __half2 h = __floats2half2_rn(a, b);
    return *reinterpret_cast<unsigned int*>(&h);
}

// ---------------------------------------------------------------------------
// K_uhat: u_hat[b,c,i,do] = sum_k W[c,i,0,do,k] * x[b,i,k]   (fp32 -> fp16)
// grid = I (block per input capsule), 256 threads = b.
// ---------------------------------------------------------------------------
__global__ __launch_bounds__(256) void uhat_kernel(
    const float* __restrict__ x, const float* __restrict__ W)
{
    const int i = blockIdx.x;
    const int b = threadIdx.x;

    __shared__ float4 Ws[CCL * DOV * 2];   // W[c,i,:,:] rows: 5120 B

    for (int f = threadIdx.x; f < CCL * DOV * 2; f += 256) {
        int c = f >> 5, rem = f & 31, d = rem >> 1, h = rem & 1;
        Ws[f] = *reinterpret_cast<const float4*>(
            W + ((((size_t)c * ICAP + i) * DOV) + d) * DIV + h * 4);
    }

    const float* xp = x + (size_t)b * (ICAP * DIV) + (size_t)i * DIV;
    const float4 x0 = *reinterpret_cast<const float4*>(xp);
    const float4 x1 = *reinterpret_cast<const float4*>(xp + 4);

    __syncthreads();

    __half* up = g_uhat + (size_t)b * (CCL * ICAP * DOV) + (size_t)i * DOV;

    #pragma unroll
    for (int c = 0; c < CCL; c++) {
        float r[DOV];
        #pragma unroll
        for (int d = 0; d < DOV; d++) {
            float4 w0 = Ws[c * 32 + d * 2];
            float4 w1 = Ws[c * 32 + d * 2 + 1];
            float v = w0.x * x0.x;
            v = fmaf(w0.y, x0.y, v); v = fmaf(w0.z, x0.z, v); v = fmaf(w0.w, x0.w, v);
            v = fmaf(w1.x, x1.x, v); v = fmaf(w1.y, x1.y, v);
            v = fmaf(w1.z, x1.z, v); v = fmaf(w1.w, x1.w, v);
            r[d] = v;
        }
        uint4 q0, q1;
        q0.x = pack_h2(r[0],  r[1]);  q0.y = pack_h2(r[2],  r[3]);
        q0.z = pack_h2(r[4],  r[5]);  q0.w = pack_h2(r[6],  r[7]);
        q1.x = pack_h2(r[8],  r[9]);  q1.y = pack_h2(r[10], r[11]);
        q1.z = pack_h2(r[12], r[13]); q1.w = pack_h2(r[14], r[15]);
        __half* o = up + (size_t)c * (ICAP * DOV);
        *reinterpret_cast<uint4*>(o)     = q0;
        *reinterpret_cast<uint4*>(o + 8) = q1;
    }
}

// unpack 2x uint4 of half2 into 16 floats and fma-accumulate w*u into sac
static __device__ __forceinline__ void unpack16(const uint4& a, const uint4& b,
                                                float* __restrict__ u) {
    const __half2* ha = reinterpret_cast<const __half2*>(&a);
    const __half2* hb = reinterpret_cast<const __half2*>(&b);
    #pragma unroll
    for (int q = 0; q < 4; q++) {
        float2 f = __half22float2(ha[q]);
        u[q * 2] = f.x; u[q * 2 + 1] = f.y;
    }
    #pragma unroll
    for (int q = 0; q < 4; q++) {
        float2 f = __half22float2(hb[q]);
        u[8 + q * 2] = f.x; u[8 + q * 2 + 1] = f.y;
    }
}

// ---------------------------------------------------------------------------
// route_kernel: all 3 routing iterations for one batch element.
// grid = B, 320 threads: warp = class c, lane = i-slot. 36 tiles per pass.
//   iter 0: w = 0.1 exactly (softmax of zeros), no barriers.
//   iters 1,2: logit = <u, vacc>; softmax across warps via double-buffered
//   smem (1 barrier/tile). vacc kept in registers per warp. Final v -> out.
// ---------------------------------------------------------------------------
__global__ __launch_bounds__(320, 2) void route_kernel(float* __restrict__ out)
{
    const int b  = blockIdx.x;
    const int c  = threadIdx.x >> 5;
    const int ii = threadIdx.x & 31;

    __shared__ float e_s[2][CCL][33];

    const __half* ub = g_uhat + ((size_t)b * CCL + c) * (size_t)ICAP * DOV;

    float vr[DOV];                      // running sum of squashed v's
    #pragma unroll
    for (int j = 0; j < DOV; j++) vr[j] = 0.0f;

    float sac[DOV];

    // ---------------- iteration 0: uniform weights 0.1, pure streaming sum
    #pragma unroll
    for (int j = 0; j < DOV; j++) sac[j] = 0.0f;
    {
        const uint4* p0 = reinterpret_cast<const uint4*>(ub + (size_t)ii * DOV);
        uint4 ua = p0[0], ux = p0[1];
        for (int ti = 0; ti < NT; ti++) {
            const int tn = (ti + 1 < NT) ? (ti + 1) : (NT - 1);
            const uint4* pn = reinterpret_cast<const uint4*>(
                ub + (size_t)(tn * 32 + ii) * DOV);
            uint4 na = pn[0], nb = pn[1];

            float u[DOV];
            unpack16(ua, ux, u);
            #pragma unroll
            for (int j = 0; j < DOV; j++) sac[j] = fmaf(0.1f, u[j], sac[j]);

            ua = na; ux = nb;
        }
    }
    // reduce + squash -> v0
    #pragma unroll
    for (int off = 16; off > 0; off >>= 1)
        #pragma unroll
        for (int j = 0; j < DOV; j++)
            sac[j] += __shfl_xor_sync(0xffffffffu, sac[j], off);
    {
        float sq = 0.0f;
        #pragma unroll
        for (int j = 0; j < DOV; j++) sq = fmaf(sac[j], sac[j], sq);
        float scale = __fdividef(sqrtf(sq), 1.0f + sq);
        #pragma unroll
        for (int j = 0; j < DOV; j++) vr[j] = sac[j] * scale;
    }

    // ---------------- iterations 1 and 2
    #pragma unroll 1
    for (int t = 1; t < 3; t++) {
        #pragma unroll
        for (int j = 0; j < DOV; j++) sac[j] = 0.0f;

        const uint4* p0 = reinterpret_cast<const uint4*>(ub + (size_t)ii * DOV);
        uint4 ua = p0[0], ux = p0[1];

        for (int ti = 0; ti < NT; ti++) {
            const int tn = (ti + 1 < NT) ? (ti + 1) : (NT - 1);
            const uint4* pn = reinterpret_cast<const uint4*>(
                ub + (size_t)(tn * 32 + ii) * DOV);
            uint4 na = pn[0], nb = pn[1];

            float u[DOV];
            unpack16(ua, ux, u);

            float a = u[0] * vr[0];
            #pragma unroll
            for (int j = 1; j < DOV; j++) a = fmaf(u[j], vr[j], a);
            // |a| bounded (~35 max): exp safe in fp32 without max-subtract
            float e = __expf(a);
            const int p = ti & 1;
            e_s[p][c][ii] = e;
            __syncthreads();
            float Z = e_s[p][0][ii];
            #pragma unroll
            for (int cc = 1; cc < CCL; cc++) Z += e_s[p][cc][ii];
            float w = __fdividef(e, Z);

            #pragma unroll
            for (int j = 0; j < DOV; j++) sac[j] = fmaf(w, u[j], sac[j]);

            ua = na; ux = nb;
        }

        #pragma unroll
        for (int off = 16; off > 0; off >>= 1)
            #pragma unroll
            for (int j = 0; j < DOV; j++)
                sac[j] += __shfl_xor_sync(0xffffffffu, sac[j], off);

        float sq = 0.0f;
        #pragma unroll
        for (int j = 0; j < DOV; j++) sq = fmaf(sac[j], sac[j], sq);
        float scale = __fdividef(sqrtf(sq), 1.0f + sq);

        if (t == 2) {
            if (ii == 0) {
                float v[DOV];
                #pragma unroll
                for (int j = 0; j < DOV; j++) v[j] = sac[j] * scale;
                float4* op = reinterpret_cast<float4*>(
                    out + ((size_t)b * CCL + c) * DOV);
                op[0] = make_float4(v[0],  v[1],  v[2],  v[3]);
                op[1] = make_float4(v[4],  v[5],  v[6],  v[7]);
                op[2] = make_float4(v[8],  v[9],  v[10], v[11]);
                op[3] = make_float4(v[12], v[13], v[14], v[15]);
            }
        } else {
            #pragma unroll
            for (int j = 0; j < DOV; j++) vr[j] += sac[j] * scale;
        }
    }
}

// ---------------------------------------------------------------------------
extern "C" void kernel_launch(void* const* d_in, const int* in_sizes, int n_in,
                              void* d_out, int out_size)
{
    const float* x = (const float*)d_in[0];
    const float* W = (const float*)d_in[1];
    if (in_sizes[0] == CCL * ICAP * DOV * DIV) {  // defensively identify by size
        const float* t = x; x = W; W = t;
    }
    float* out = (float*)d_out;

    uhat_kernel<<<ICAP, 256>>>(x, W);
    route_kernel<<<BSZ, 320>>>(out);
}